// round 2
// baseline (speedup 1.0000x reference)
#include <cuda_runtime.h>
#include <math.h>

// Problem constants
#define DMODEL 1024
#define NHEAD  16
#define HD     64
#define BATCH  4
#define SEQ    2048
#define NTOK   (BATCH * SEQ)          // 8192
#define QKVROW (3 * DMODEL)           // 3072

// Scratch (device globals: allocation-guard safe)
__device__ float g_qkv[(size_t)NTOK * QKVROW];  // [8192, 3072]
__device__ float g_y[(size_t)NTOK * DMODEL];    // [8192, 1024]

// ---------------------------------------------------------------------------
// SGEMM: C[M,N] = A[M,K] @ B[K,N], all fp32 row-major.
// 128x128 block tile, BK=16, 8x8 per-thread micro tile, 256 threads.
// ---------------------------------------------------------------------------
#define BM 128
#define BN 128
#define BK 16
#define TM 8
#define TN 8

__global__ void __launch_bounds__(256) sgemm_kernel(
    const float* __restrict__ A, const float* __restrict__ B,
    float* __restrict__ C, int M, int N, int K)
{
    __shared__ float As[BK][BM];   // A stored transposed: As[k][m]
    __shared__ float Bs[BK][BN];

    const int tid = threadIdx.x;
    const int bx = blockIdx.x;     // N tile
    const int by = blockIdx.y;     // M tile

    const int trow = tid >> 4;     // 0..15 (M direction)
    const int tcol = tid & 15;     // 0..15 (N direction)

    // A tile loads: 128 rows x 16 cols. thread -> (row = tid/4 and +64, col4 = (tid%4)*4)
    const int arow  = tid >> 2;          // 0..63
    const int acol4 = (tid & 3) << 2;    // 0,4,8,12
    // B tile loads: 16 rows x 128 cols. thread -> (row = tid/32 and +8, col = (tid%32)*4)
    const int brow = tid >> 5;           // 0..7
    const int bcol = (tid & 31) << 2;    // 0..124

    const float* Ag = A + (size_t)(by * BM) * K;
    const float* Bg = B + (size_t)(bx * BN);

    float acc[TM][TN];
    #pragma unroll
    for (int i = 0; i < TM; i++)
        #pragma unroll
        for (int j = 0; j < TN; j++) acc[i][j] = 0.0f;

    for (int k0 = 0; k0 < K; k0 += BK) {
        float4 a0 = *(const float4*)(Ag + (size_t)arow        * K + k0 + acol4);
        float4 a1 = *(const float4*)(Ag + (size_t)(arow + 64) * K + k0 + acol4);
        float4 b0 = *(const float4*)(Bg + (size_t)(k0 + brow    ) * N + bcol);
        float4 b1 = *(const float4*)(Bg + (size_t)(k0 + brow + 8) * N + bcol);

        __syncthreads();  // protect previous iteration's readers

        As[acol4 + 0][arow] = a0.x;
        As[acol4 + 1][arow] = a0.y;
        As[acol4 + 2][arow] = a0.z;
        As[acol4 + 3][arow] = a0.w;
        As[acol4 + 0][arow + 64] = a1.x;
        As[acol4 + 1][arow + 64] = a1.y;
        As[acol4 + 2][arow + 64] = a1.z;
        As[acol4 + 3][arow + 64] = a1.w;
        *(float4*)&Bs[brow    ][bcol] = b0;
        *(float4*)&Bs[brow + 8][bcol] = b1;

        __syncthreads();

        #pragma unroll
        for (int kk = 0; kk < BK; kk++) {
            float a[TM], b[TN];
            *(float4*)&a[0] = *(const float4*)&As[kk][trow * TM];
            *(float4*)&a[4] = *(const float4*)&As[kk][trow * TM + 4];
            *(float4*)&b[0] = *(const float4*)&Bs[kk][tcol * TN];
            *(float4*)&b[4] = *(const float4*)&Bs[kk][tcol * TN + 4];
            #pragma unroll
            for (int i = 0; i < TM; i++)
                #pragma unroll
                for (int j = 0; j < TN; j++)
                    acc[i][j] = fmaf(a[i], b[j], acc[i][j]);
        }
    }

    float* Cg = C + (size_t)(by * BM + trow * TM) * N + bx * BN + tcol * TN;
    #pragma unroll
    for (int i = 0; i < TM; i++) {
        *(float4*)(Cg + (size_t)i * N)     = *(float4*)&acc[i][0];
        *(float4*)(Cg + (size_t)i * N + 4) = *(float4*)&acc[i][4];
    }
}

// ---------------------------------------------------------------------------
// Flash attention (causal): per-block: 64 queries of one (batch, head).
// Grid: (qtile=32, head=16, batch=4), 256 threads.
// SMEM: Qt[d][q] 16KB, KP 16KB (Kt[d][k] then P[q][k]), Vs[k][d] 16KB = 48KB.
// Thread (tx,ty): tx = tid&15 (key/dim dir), ty = tid>>4 (query dir).
// Owns S[q=ty*4+i][k=tx*4+j] and O[q=ty*4+i][d=tx*4+j].
// Row stats (m,l) replicated across the 16 tx lanes via width-16 shuffles.
// ---------------------------------------------------------------------------
__global__ void __launch_bounds__(256) attn_kernel(
    const float* __restrict__ qkv, float* __restrict__ y)
{
    __shared__ float Qt[HD][64];       // [d][q]
    __shared__ float KP[64 * 64];      // Kt[d][k]  /  later P[q][k]
    __shared__ float Vs[64][64];       // [k][d]

    const int tid = threadIdx.x;
    const int tx = tid & 15;
    const int ty = tid >> 4;
    const int qt = blockIdx.x;
    const int h  = blockIdx.y;
    const int b  = blockIdx.z;
    const int q0 = qt * 64;

    const float* Qg = qkv + (size_t)(b * SEQ) * QKVROW + h * HD;              // Q cols
    const float* Kg = Qg + DMODEL;                                            // K cols
    const float* Vg = Qg + 2 * DMODEL;                                        // V cols

    // Load Q tile transposed: Qt[d][q]
    {
        const int q  = tid >> 2;            // 0..63
        const int d4b = (tid & 3);          // 0..3
        #pragma unroll
        for (int it = 0; it < 4; it++) {
            const int d4 = d4b + it * 4;    // 0..15
            float4 v = *(const float4*)(Qg + (size_t)(q0 + q) * QKVROW + d4 * 4);
            Qt[d4 * 4 + 0][q] = v.x;
            Qt[d4 * 4 + 1][q] = v.y;
            Qt[d4 * 4 + 2][q] = v.z;
            Qt[d4 * 4 + 3][q] = v.w;
        }
    }

    float m[4], l[4], O[4][4];
    #pragma unroll
    for (int i = 0; i < 4; i++) {
        m[i] = -INFINITY;
        l[i] = 0.0f;
        #pragma unroll
        for (int j = 0; j < 4; j++) O[i][j] = 0.0f;
    }

    const float sc = 0.125f * 1.44269504088896f;   // 1/sqrt(64) * log2(e)

    for (int kt = 0; kt <= qt; kt++) {
        __syncthreads();   // previous iteration's P/V readers done (also orders Qt on kt=0)

        // Load K transposed -> KP as Kt[d][k]; V natural -> Vs[k][d]
        {
            const int r   = tid >> 2;      // key row in tile 0..63
            const int d4b = (tid & 3);
            const int tok = kt * 64 + r;
            #pragma unroll
            for (int it = 0; it < 4; it++) {
                const int d4 = d4b + it * 4;
                float4 kv = *(const float4*)(Kg + (size_t)tok * QKVROW + d4 * 4);
                KP[(d4 * 4 + 0) * 64 + r] = kv.x;
                KP[(d4 * 4 + 1) * 64 + r] = kv.y;
                KP[(d4 * 4 + 2) * 64 + r] = kv.z;
                KP[(d4 * 4 + 3) * 64 + r] = kv.w;
                float4 vv = *(const float4*)(Vg + (size_t)tok * QKVROW + d4 * 4);
                *(float4*)&Vs[r][d4 * 4] = vv;
            }
        }
        __syncthreads();

        // S = Q @ K^T (scaled into log2 domain)
        float S[4][4];
        #pragma unroll
        for (int i = 0; i < 4; i++)
            #pragma unroll
            for (int j = 0; j < 4; j++) S[i][j] = 0.0f;

        #pragma unroll
        for (int d = 0; d < HD; d++) {
            float qv[4], kv[4];
            *(float4*)qv = *(const float4*)&Qt[d][ty * 4];
            *(float4*)kv = *(const float4*)&KP[d * 64 + tx * 4];
            #pragma unroll
            for (int i = 0; i < 4; i++)
                #pragma unroll
                for (int j = 0; j < 4; j++)
                    S[i][j] = fmaf(qv[i], kv[j], S[i][j]);
        }

        // scale + causal mask
        const bool diag = (kt == qt);
        #pragma unroll
        for (int i = 0; i < 4; i++) {
            const int qg = q0 + ty * 4 + i;
            #pragma unroll
            for (int j = 0; j < 4; j++) {
                float s = S[i][j] * sc;
                if (diag) {
                    const int kg = kt * 64 + tx * 4 + j;
                    if (kg > qg) s = -INFINITY;
                }
                S[i][j] = s;
            }
        }

        // row max (over j, then over the 16 tx lanes; width-16 segmented shuffle)
        float rmax[4];
        #pragma unroll
        for (int i = 0; i < 4; i++) {
            float v = fmaxf(fmaxf(S[i][0], S[i][1]), fmaxf(S[i][2], S[i][3]));
            #pragma unroll
            for (int off = 8; off > 0; off >>= 1)
                v = fmaxf(v, __shfl_xor_sync(0xffffffffu, v, off, 16));
            rmax[i] = v;
        }

        float alpha[4];
        #pragma unroll
        for (int i = 0; i < 4; i++) {
            const float mn = fmaxf(m[i], rmax[i]);
            alpha[i] = exp2f(m[i] - mn);
            m[i] = mn;
        }

        // probs + row sum
        float rsum[4];
        #pragma unroll
        for (int i = 0; i < 4; i++) {
            float s = 0.0f;
            #pragma unroll
            for (int j = 0; j < 4; j++) {
                const float p = exp2f(S[i][j] - m[i]);
                S[i][j] = p;
                s += p;
            }
            #pragma unroll
            for (int off = 8; off > 0; off >>= 1)
                s += __shfl_xor_sync(0xffffffffu, s, off, 16);
            rsum[i] = s;
        }

        #pragma unroll
        for (int i = 0; i < 4; i++) {
            l[i] = l[i] * alpha[i] + rsum[i];
            #pragma unroll
            for (int j = 0; j < 4; j++) O[i][j] *= alpha[i];
        }

        __syncthreads();   // all reads of KP (as Kt) complete

        // write P into KP as P[q][k]
        #pragma unroll
        for (int i = 0; i < 4; i++)
            *(float4*)&KP[(ty * 4 + i) * 64 + tx * 4] = *(float4*)&S[i][0];

        __syncthreads();

        // O += P @ V
        #pragma unroll
        for (int k = 0; k < 64; k++) {
            float pv[4], vv[4];
            #pragma unroll
            for (int i = 0; i < 4; i++) pv[i] = KP[(ty * 4 + i) * 64 + k];
            *(float4*)vv = *(const float4*)&Vs[k][tx * 4];
            #pragma unroll
            for (int i = 0; i < 4; i++)
                #pragma unroll
                for (int j = 0; j < 4; j++)
                    O[i][j] = fmaf(pv[i], vv[j], O[i][j]);
        }
    }

    // normalize + store to y[b*SEQ + q][h*HD + d]
    #pragma unroll
    for (int i = 0; i < 4; i++) {
        const float inv = 1.0f / l[i];
        float4 o;
        o.x = O[i][0] * inv;
        o.y = O[i][1] * inv;
        o.z = O[i][2] * inv;
        o.w = O[i][3] * inv;
        const size_t row = (size_t)(b * SEQ + q0 + ty * 4 + i);
        *(float4*)(y + row * DMODEL + h * HD + tx * 4) = o;
    }
}

// ---------------------------------------------------------------------------
// Launch
// ---------------------------------------------------------------------------
extern "C" void kernel_launch(void* const* d_in, const int* in_sizes, int n_in,
                              void* d_out, int out_size)
{
    const float* x      = (const float*)d_in[0];   // [4,2048,1024]
    const float* W_attn = (const float*)d_in[1];   // [1024,3072]
    const float* W_proj = (const float*)d_in[2];   // [1024,1024]
    float* out = (float*)d_out;                    // [4,2048,1024]

    void* p_qkv = nullptr;
    void* p_y   = nullptr;
    cudaGetSymbolAddress(&p_qkv, g_qkv);
    cudaGetSymbolAddress(&p_y,   g_y);
    float* qkv = (float*)p_qkv;
    float* y   = (float*)p_y;

    // 1) qkv = x @ W_attn     [8192,1024] @ [1024,3072]
    {
        dim3 grid(QKVROW / BN, NTOK / BM);
        sgemm_kernel<<<grid, 256>>>(x, W_attn, qkv, NTOK, QKVROW, DMODEL);
    }

    // 2) y = causal_attention(qkv)
    {
        dim3 grid(SEQ / 64, NHEAD, BATCH);
        attn_kernel<<<grid, 256>>>(qkv, y);
    }

    // 3) out = y @ W_proj     [8192,1024] @ [1024,1024]
    {
        dim3 grid(DMODEL / BN, NTOK / BM);
        sgemm_kernel<<<grid, 256>>>(y, W_proj, out, NTOK, DMODEL, DMODEL);
    }
}

// round 4
// speedup vs baseline: 1.3682x; 1.3682x over previous
#include <cuda_runtime.h>
#include <cuda_bf16.h>
#include <math.h>
#include <stdint.h>

// Problem constants
#define DMODEL 1024
#define NHEAD  16
#define HD     64
#define BATCH  4
#define SEQ    2048
#define NTOK   (BATCH * SEQ)          // 8192
#define QKVROW (3 * DMODEL)           // 3072

// Scratch (device globals: allocation-guard safe)
__device__ float g_qkv[(size_t)NTOK * QKVROW];      // [8192, 3072]
__device__ float g_y[(size_t)NTOK * DMODEL];        // [8192, 1024]
__device__ float g_wattnT[(size_t)QKVROW * DMODEL]; // [3072, 1024] = W_attn^T
__device__ float g_wprojT[(size_t)DMODEL * DMODEL]; // [1024, 1024] = W_proj^T

// ---------------------------------------------------------------------------
// Warp-level MMA helpers (sm_80-era PTX: safe for non-'a' PTX target)
// ---------------------------------------------------------------------------
__device__ __forceinline__ uint32_t smem_u32(const void* p) {
    uint32_t a;
    asm("{ .reg .u64 t; cvta.to.shared.u64 t, %1; cvt.u32.u64 %0, t; }"
        : "=r"(a) : "l"(p));
    return a;
}

__device__ __forceinline__ void ldsm4(uint32_t* r, uint32_t addr) {
    asm volatile("ldmatrix.sync.aligned.m8n8.x4.shared.b16 {%0,%1,%2,%3}, [%4];"
        : "=r"(r[0]), "=r"(r[1]), "=r"(r[2]), "=r"(r[3]) : "r"(addr));
}

__device__ __forceinline__ void mma_bf16(float* c, const uint32_t* a,
                                         const uint32_t* b) {
    asm volatile(
        "mma.sync.aligned.m16n8k16.row.col.f32.bf16.bf16.f32 "
        "{%0,%1,%2,%3}, {%4,%5,%6,%7}, {%8,%9}, {%0,%1,%2,%3};"
        : "+f"(c[0]), "+f"(c[1]), "+f"(c[2]), "+f"(c[3])
        : "r"(a[0]), "r"(a[1]), "r"(a[2]), "r"(a[3]), "r"(b[0]), "r"(b[1]));
}

__device__ __forceinline__ uint32_t packbf(__nv_bfloat16 a, __nv_bfloat16 b) {
    __nv_bfloat162 t = __halves2bfloat162(a, b);   // a = low (first element)
    return *(uint32_t*)&t;
}

// split float4 -> hi/lo bf16 pairs (x = hi + lo to ~16 mantissa bits)
__device__ __forceinline__ void split4(float4 v, uint2& hi, uint2& lo) {
    __nv_bfloat16 hx = __float2bfloat16_rn(v.x);
    __nv_bfloat16 hy = __float2bfloat16_rn(v.y);
    __nv_bfloat16 hz = __float2bfloat16_rn(v.z);
    __nv_bfloat16 hw = __float2bfloat16_rn(v.w);
    __nv_bfloat16 lx = __float2bfloat16_rn(v.x - __bfloat162float(hx));
    __nv_bfloat16 ly = __float2bfloat16_rn(v.y - __bfloat162float(hy));
    __nv_bfloat16 lz = __float2bfloat16_rn(v.z - __bfloat162float(hz));
    __nv_bfloat16 lw = __float2bfloat16_rn(v.w - __bfloat162float(hw));
    hi.x = packbf(hx, hy); hi.y = packbf(hz, hw);
    lo.x = packbf(lx, ly); lo.y = packbf(lz, lw);
}

// ---------------------------------------------------------------------------
// Transpose: Wt[n][k] = W[k][n].  W is [K,N].
// ---------------------------------------------------------------------------
__global__ void __launch_bounds__(256) transpose_kernel(
    const float* __restrict__ W, float* __restrict__ Wt, int K, int N)
{
    __shared__ float t[32][33];
    const int tx = threadIdx.x;   // 0..31
    const int ty = threadIdx.y;   // 0..7
    const int n0 = blockIdx.x * 32;
    const int k0 = blockIdx.y * 32;
    #pragma unroll
    for (int j = 0; j < 32; j += 8)
        t[ty + j][tx] = W[(size_t)(k0 + ty + j) * N + n0 + tx];
    __syncthreads();
    #pragma unroll
    for (int j = 0; j < 32; j += 8)
        Wt[(size_t)(n0 + ty + j) * K + k0 + tx] = t[tx][ty + j];
}

// ---------------------------------------------------------------------------
// Tensor-core GEMM via mma.sync bf16 3-term split.
// C[M,N] = A[M,K] @ Bt[N,K]^T, fp32 in/out.
// 128x128 CTA tile, BK=32, 8 warps (2m x 4n), warp tile 64x32.
// SMEM regions per buffer (row stride 40 bf16 = 80B, conflict-free ldmatrix):
//   A_hi, A_lo, B_hi, B_lo : 128 rows x 80B = 10240B each -> 40960B/buffer.
// ---------------------------------------------------------------------------
#define GSTRIDE   80          // bytes per SMEM row (40 bf16)
#define REG_B     (128 * GSTRIDE)   // 10240
#define BUF_B     (4 * REG_B)       // 40960
#define SMEM_DYN  (2 * BUF_B)       // 81920

__global__ void __launch_bounds__(256) tc_mma_gemm(
    const float* __restrict__ A, const float* __restrict__ Bt,
    float* __restrict__ C, int M, int N, int K)
{
    extern __shared__ __align__(16) char dsm[];

    const int tid = threadIdx.x;
    const int wid = tid >> 5;
    const int lid = tid & 31;
    const int m0 = blockIdx.y * 128;
    const int n0 = blockIdx.x * 128;

    const int wm = wid >> 2;          // 0..1
    const int wn = wid & 3;           // 0..3
    const int Wm = wm * 64;
    const int Wn = wn * 32;

    const uint32_t sbase = smem_u32(dsm);

    // global loader mapping: 8 threads/row, 32 rows/pass, 4 passes
    const int grow = tid >> 3;           // 0..31
    const int gcol = (tid & 7) * 4;      // float col 0..28
    const uint32_t soff = (uint32_t)grow * GSTRIDE + (uint32_t)(tid & 7) * 8;

    // ldmatrix lane addressing
    const int l16 = lid & 15;
    const int kh  = lid >> 4;            // A: k-half
    const int bl8 = lid & 7;
    const int bkh = (lid >> 3) & 1;      // B: k-half
    const int bnh = lid >> 4;            // B: n-half

    float acc[4][4][4];                  // [mt][nt][frag]
    #pragma unroll
    for (int i = 0; i < 4; i++)
        #pragma unroll
        for (int j = 0; j < 4; j++)
            #pragma unroll
            for (int c = 0; c < 4; c++) acc[i][j][c] = 0.0f;

    const int NIT = K >> 5;
    float4 av[4], bv[4];

    // ---- load tile 0 ----
    #pragma unroll
    for (int r = 0; r < 4; r++) {
        av[r] = *(const float4*)(A  + (size_t)(m0 + grow + 32 * r) * K + gcol);
        bv[r] = *(const float4*)(Bt + (size_t)(n0 + grow + 32 * r) * K + gcol);
    }
    {
        char* sb = dsm;  // buffer 0
        #pragma unroll
        for (int r = 0; r < 4; r++) {
            uint2 hi, lo;
            const uint32_t o = soff + (uint32_t)(32 * r) * GSTRIDE;
            split4(av[r], hi, lo);
            *(uint2*)(sb + 0 * REG_B + o) = hi;
            *(uint2*)(sb + 1 * REG_B + o) = lo;
            split4(bv[r], hi, lo);
            *(uint2*)(sb + 2 * REG_B + o) = hi;
            *(uint2*)(sb + 3 * REG_B + o) = lo;
        }
    }
    __syncthreads();

    for (int it = 0; it < NIT; it++) {
        // prefetch next tile
        if (it + 1 < NIT) {
            const int k0 = (it + 1) * 32;
            #pragma unroll
            for (int r = 0; r < 4; r++) {
                av[r] = *(const float4*)(A  + (size_t)(m0 + grow + 32 * r) * K + k0 + gcol);
                bv[r] = *(const float4*)(Bt + (size_t)(n0 + grow + 32 * r) * K + k0 + gcol);
            }
        }

        // compute on buffer it&1
        const uint32_t buf = sbase + (uint32_t)(it & 1) * BUF_B;
        #pragma unroll
        for (int ks = 0; ks < 2; ks++) {
            const uint32_t akoff = (uint32_t)(ks * 16 + kh * 8) * 2;
            const uint32_t bkoff = (uint32_t)(ks * 16 + bkh * 8) * 2;

            uint32_t ah[4][4], al[4][4];
            #pragma unroll
            for (int mt = 0; mt < 4; mt++) {
                const uint32_t row = (uint32_t)(Wm + mt * 16 + l16) * GSTRIDE + akoff;
                ldsm4(ah[mt], buf + 0 * REG_B + row);
                ldsm4(al[mt], buf + 1 * REG_B + row);
            }
            uint32_t bh[2][4], bl[2][4];
            #pragma unroll
            for (int ng = 0; ng < 2; ng++) {
                const uint32_t row =
                    (uint32_t)(Wn + ng * 16 + bl8 + bnh * 8) * GSTRIDE + bkoff;
                ldsm4(bh[ng], buf + 2 * REG_B + row);
                ldsm4(bl[ng], buf + 3 * REG_B + row);
            }

            #pragma unroll
            for (int mt = 0; mt < 4; mt++)
                #pragma unroll
                for (int ng = 0; ng < 2; ng++)
                    #pragma unroll
                    for (int hf = 0; hf < 2; hf++) {
                        float* c = acc[mt][ng * 2 + hf];
                        const uint32_t bfh[2] = { bh[ng][hf * 2], bh[ng][hf * 2 + 1] };
                        const uint32_t bfl[2] = { bl[ng][hf * 2], bl[ng][hf * 2 + 1] };
                        mma_bf16(c, ah[mt], bfh);   // hi*hi
                        mma_bf16(c, ah[mt], bfl);   // hi*lo
                        mma_bf16(c, al[mt], bfh);   // lo*hi
                    }
        }
        __syncthreads();

        // store prefetched tile into the other buffer
        if (it + 1 < NIT) {
            char* sb = dsm + ((it + 1) & 1) * BUF_B;
            #pragma unroll
            for (int r = 0; r < 4; r++) {
                uint2 hi, lo;
                const uint32_t o = soff + (uint32_t)(32 * r) * GSTRIDE;
                split4(av[r], hi, lo);
                *(uint2*)(sb + 0 * REG_B + o) = hi;
                *(uint2*)(sb + 1 * REG_B + o) = lo;
                split4(bv[r], hi, lo);
                *(uint2*)(sb + 2 * REG_B + o) = hi;
                *(uint2*)(sb + 3 * REG_B + o) = lo;
            }
            __syncthreads();
        }
    }

    // epilogue
    const int g  = lid >> 2;
    const int tg = (lid & 3) * 2;
    #pragma unroll
    for (int mt = 0; mt < 4; mt++) {
        #pragma unroll
        for (int nt = 0; nt < 4; nt++) {
            const int mrow = m0 + Wm + mt * 16 + g;
            const int ncol = n0 + Wn + nt * 8 + tg;
            float2 v0 = make_float2(acc[mt][nt][0], acc[mt][nt][1]);
            float2 v1 = make_float2(acc[mt][nt][2], acc[mt][nt][3]);
            *(float2*)(C + (size_t)mrow * N + ncol)       = v0;
            *(float2*)(C + (size_t)(mrow + 8) * N + ncol) = v1;
        }
    }
}

// ---------------------------------------------------------------------------
// Flash attention (causal) — unchanged from R1 (fp32 FMA).
// ---------------------------------------------------------------------------
__global__ void __launch_bounds__(256) attn_kernel(
    const float* __restrict__ qkv, float* __restrict__ y)
{
    __shared__ float Qt[HD][64];       // [d][q]
    __shared__ float KP[64 * 64];      // Kt[d][k]  /  later P[q][k]
    __shared__ float Vs[64][64];       // [k][d]

    const int tid = threadIdx.x;
    const int tx = tid & 15;
    const int ty = tid >> 4;
    const int qt = blockIdx.x;
    const int h  = blockIdx.y;
    const int b  = blockIdx.z;
    const int q0 = qt * 64;

    const float* Qg = qkv + (size_t)(b * SEQ) * QKVROW + h * HD;
    const float* Kg = Qg + DMODEL;
    const float* Vg = Qg + 2 * DMODEL;

    {
        const int q  = tid >> 2;
        const int d4b = (tid & 3);
        #pragma unroll
        for (int it = 0; it < 4; it++) {
            const int d4 = d4b + it * 4;
            float4 v = *(const float4*)(Qg + (size_t)(q0 + q) * QKVROW + d4 * 4);
            Qt[d4 * 4 + 0][q] = v.x;
            Qt[d4 * 4 + 1][q] = v.y;
            Qt[d4 * 4 + 2][q] = v.z;
            Qt[d4 * 4 + 3][q] = v.w;
        }
    }

    float m[4], l[4], O[4][4];
    #pragma unroll
    for (int i = 0; i < 4; i++) {
        m[i] = -INFINITY;
        l[i] = 0.0f;
        #pragma unroll
        for (int j = 0; j < 4; j++) O[i][j] = 0.0f;
    }

    const float sc = 0.125f * 1.44269504088896f;

    for (int kt = 0; kt <= qt; kt++) {
        __syncthreads();

        {
            const int r   = tid >> 2;
            const int d4b = (tid & 3);
            const int tok = kt * 64 + r;
            #pragma unroll
            for (int it = 0; it < 4; it++) {
                const int d4 = d4b + it * 4;
                float4 kv = *(const float4*)(Kg + (size_t)tok * QKVROW + d4 * 4);
                KP[(d4 * 4 + 0) * 64 + r] = kv.x;
                KP[(d4 * 4 + 1) * 64 + r] = kv.y;
                KP[(d4 * 4 + 2) * 64 + r] = kv.z;
                KP[(d4 * 4 + 3) * 64 + r] = kv.w;
                float4 vv = *(const float4*)(Vg + (size_t)tok * QKVROW + d4 * 4);
                *(float4*)&Vs[r][d4 * 4] = vv;
            }
        }
        __syncthreads();

        float S[4][4];
        #pragma unroll
        for (int i = 0; i < 4; i++)
            #pragma unroll
            for (int j = 0; j < 4; j++) S[i][j] = 0.0f;

        #pragma unroll
        for (int d = 0; d < HD; d++) {
            float qv[4], kv[4];
            *(float4*)qv = *(const float4*)&Qt[d][ty * 4];
            *(float4*)kv = *(const float4*)&KP[d * 64 + tx * 4];
            #pragma unroll
            for (int i = 0; i < 4; i++)
                #pragma unroll
                for (int j = 0; j < 4; j++)
                    S[i][j] = fmaf(qv[i], kv[j], S[i][j]);
        }

        const bool diag = (kt == qt);
        #pragma unroll
        for (int i = 0; i < 4; i++) {
            const int qg = q0 + ty * 4 + i;
            #pragma unroll
            for (int j = 0; j < 4; j++) {
                float s = S[i][j] * sc;
                if (diag) {
                    const int kg = kt * 64 + tx * 4 + j;
                    if (kg > qg) s = -INFINITY;
                }
                S[i][j] = s;
            }
        }

        float rmax[4];
        #pragma unroll
        for (int i = 0; i < 4; i++) {
            float v = fmaxf(fmaxf(S[i][0], S[i][1]), fmaxf(S[i][2], S[i][3]));
            #pragma unroll
            for (int off = 8; off > 0; off >>= 1)
                v = fmaxf(v, __shfl_xor_sync(0xffffffffu, v, off, 16));
            rmax[i] = v;
        }

        float alpha[4];
        #pragma unroll
        for (int i = 0; i < 4; i++) {
            const float mn = fmaxf(m[i], rmax[i]);
            alpha[i] = exp2f(m[i] - mn);
            m[i] = mn;
        }

        float rsum[4];
        #pragma unroll
        for (int i = 0; i < 4; i++) {
            float s = 0.0f;
            #pragma unroll
            for (int j = 0; j < 4; j++) {
                const float p = exp2f(S[i][j] - m[i]);
                S[i][j] = p;
                s += p;
            }
            #pragma unroll
            for (int off = 8; off > 0; off >>= 1)
                s += __shfl_xor_sync(0xffffffffu, s, off, 16);
            rsum[i] = s;
        }

        #pragma unroll
        for (int i = 0; i < 4; i++) {
            l[i] = l[i] * alpha[i] + rsum[i];
            #pragma unroll
            for (int j = 0; j < 4; j++) O[i][j] *= alpha[i];
        }

        __syncthreads();

        #pragma unroll
        for (int i = 0; i < 4; i++)
            *(float4*)&KP[(ty * 4 + i) * 64 + tx * 4] = *(float4*)&S[i][0];

        __syncthreads();

        #pragma unroll
        for (int k = 0; k < 64; k++) {
            float pv[4], vv[4];
            #pragma unroll
            for (int i = 0; i < 4; i++) pv[i] = KP[(ty * 4 + i) * 64 + k];
            *(float4*)vv = *(const float4*)&Vs[k][tx * 4];
            #pragma unroll
            for (int i = 0; i < 4; i++)
                #pragma unroll
                for (int j = 0; j < 4; j++)
                    O[i][j] = fmaf(pv[i], vv[j], O[i][j]);
        }
    }

    #pragma unroll
    for (int i = 0; i < 4; i++) {
        const float inv = 1.0f / l[i];
        float4 o;
        o.x = O[i][0] * inv;
        o.y = O[i][1] * inv;
        o.z = O[i][2] * inv;
        o.w = O[i][3] * inv;
        const size_t row = (size_t)(b * SEQ + q0 + ty * 4 + i);
        *(float4*)(y + row * DMODEL + h * HD + tx * 4) = o;
    }
}

// ---------------------------------------------------------------------------
// Launch
// ---------------------------------------------------------------------------
extern "C" void kernel_launch(void* const* d_in, const int* in_sizes, int n_in,
                              void* d_out, int out_size)
{
    const float* x      = (const float*)d_in[0];   // [4,2048,1024]
    const float* W_attn = (const float*)d_in[1];   // [1024,3072]
    const float* W_proj = (const float*)d_in[2];   // [1024,1024]
    float* out = (float*)d_out;                    // [4,2048,1024]

    void *p_qkv = nullptr, *p_y = nullptr, *p_wa = nullptr, *p_wp = nullptr;
    cudaGetSymbolAddress(&p_qkv, g_qkv);
    cudaGetSymbolAddress(&p_y,   g_y);
    cudaGetSymbolAddress(&p_wa,  g_wattnT);
    cudaGetSymbolAddress(&p_wp,  g_wprojT);
    float* qkv = (float*)p_qkv;
    float* y   = (float*)p_y;
    float* waT = (float*)p_wa;
    float* wpT = (float*)p_wp;

    cudaFuncSetAttribute(tc_mma_gemm,
                         cudaFuncAttributeMaxDynamicSharedMemorySize, SMEM_DYN);

    // 0) transpose weights to [N,K]
    {
        dim3 blk(32, 8);
        transpose_kernel<<<dim3(QKVROW / 32, DMODEL / 32), blk>>>(W_attn, waT, DMODEL, QKVROW);
        transpose_kernel<<<dim3(DMODEL / 32, DMODEL / 32), blk>>>(W_proj, wpT, DMODEL, DMODEL);
    }

    // 1) qkv = x @ W_attn   (mma.sync bf16 3-term)
    {
        dim3 grid(QKVROW / 128, NTOK / 128);
        tc_mma_gemm<<<grid, 256, SMEM_DYN>>>(x, waT, qkv, NTOK, QKVROW, DMODEL);
    }

    // 2) y = causal_attention(qkv)
    {
        dim3 grid(SEQ / 64, NHEAD, BATCH);
        attn_kernel<<<grid, 256>>>(qkv, y);
    }

    // 3) out = y @ W_proj   (mma.sync bf16 3-term)
    {
        dim3 grid(DMODEL / 128, NTOK / 128);
        tc_mma_gemm<<<grid, 256, SMEM_DYN>>>(y, wpT, out, NTOK, DMODEL, DMODEL);
    }
}

// round 5
// speedup vs baseline: 2.1230x; 1.5517x over previous
#include <cuda_runtime.h>
#include <cuda_bf16.h>
#include <math.h>
#include <stdint.h>

// Problem constants
#define DMODEL 1024
#define NHEAD  16
#define HD     64
#define BATCH  4
#define SEQ    2048
#define NTOK   (BATCH * SEQ)          // 8192
#define QKVROW (3 * DMODEL)           // 3072

// Scratch (device globals: allocation-guard safe)
__device__ float g_qkv[(size_t)NTOK * QKVROW];      // [8192, 3072]
__device__ float g_y[(size_t)NTOK * DMODEL];        // [8192, 1024]
__device__ float g_wattnT[(size_t)QKVROW * DMODEL]; // W_attn^T
__device__ float g_wprojT[(size_t)DMODEL * DMODEL]; // W_proj^T
// Split bf16 operands for attention
__device__ __nv_bfloat16 g_qh[(size_t)NTOK * DMODEL];
__device__ __nv_bfloat16 g_ql[(size_t)NTOK * DMODEL];
__device__ __nv_bfloat16 g_kh[(size_t)NTOK * DMODEL];
__device__ __nv_bfloat16 g_kl[(size_t)NTOK * DMODEL];
__device__ __nv_bfloat16 g_vth[(size_t)BATCH * NHEAD * HD * SEQ]; // [b,h,d,T]
__device__ __nv_bfloat16 g_vtl[(size_t)BATCH * NHEAD * HD * SEQ];

// ---------------------------------------------------------------------------
// PTX helpers (all sm_80-era: valid for non-'a' PTX target)
// ---------------------------------------------------------------------------
__device__ __forceinline__ uint32_t smem_u32(const void* p) {
    uint32_t a;
    asm("{ .reg .u64 t; cvta.to.shared.u64 t, %1; cvt.u32.u64 %0, t; }"
        : "=r"(a) : "l"(p));
    return a;
}

__device__ __forceinline__ void ldsm4(uint32_t* r, uint32_t addr) {
    asm volatile("ldmatrix.sync.aligned.m8n8.x4.shared.b16 {%0,%1,%2,%3}, [%4];"
        : "=r"(r[0]), "=r"(r[1]), "=r"(r[2]), "=r"(r[3]) : "r"(addr));
}

__device__ __forceinline__ void mma_bf16(float* c, const uint32_t* a,
                                         const uint32_t* b) {
    asm volatile(
        "mma.sync.aligned.m16n8k16.row.col.f32.bf16.bf16.f32 "
        "{%0,%1,%2,%3}, {%4,%5,%6,%7}, {%8,%9}, {%0,%1,%2,%3};"
        : "+f"(c[0]), "+f"(c[1]), "+f"(c[2]), "+f"(c[3])
        : "r"(a[0]), "r"(a[1]), "r"(a[2]), "r"(a[3]), "r"(b[0]), "r"(b[1]));
}

__device__ __forceinline__ void cp16(uint32_t dst, const void* src) {
    asm volatile("cp.async.cg.shared.global [%0], [%1], 16;"
        :: "r"(dst), "l"(src));
}
#define CP_COMMIT() asm volatile("cp.async.commit_group;" ::: "memory")
#define CP_WAIT1()  asm volatile("cp.async.wait_group 1;" ::: "memory")
#define CP_WAIT0()  asm volatile("cp.async.wait_group 0;" ::: "memory")

__device__ __forceinline__ uint32_t packbf(__nv_bfloat16 a, __nv_bfloat16 b) {
    __nv_bfloat162 t = __halves2bfloat162(a, b);
    return *(uint32_t*)&t;
}

__device__ __forceinline__ void split4(float4 v, uint2& hi, uint2& lo) {
    __nv_bfloat16 hx = __float2bfloat16_rn(v.x);
    __nv_bfloat16 hy = __float2bfloat16_rn(v.y);
    __nv_bfloat16 hz = __float2bfloat16_rn(v.z);
    __nv_bfloat16 hw = __float2bfloat16_rn(v.w);
    __nv_bfloat16 lx = __float2bfloat16_rn(v.x - __bfloat162float(hx));
    __nv_bfloat16 ly = __float2bfloat16_rn(v.y - __bfloat162float(hy));
    __nv_bfloat16 lz = __float2bfloat16_rn(v.z - __bfloat162float(hz));
    __nv_bfloat16 lw = __float2bfloat16_rn(v.w - __bfloat162float(hw));
    hi.x = packbf(hx, hy); hi.y = packbf(hz, hw);
    lo.x = packbf(lx, ly); lo.y = packbf(lz, lw);
}

__device__ __forceinline__ uint32_t ld32(const __nv_bfloat16* p) {
    return *(const uint32_t*)p;
}

// ---------------------------------------------------------------------------
// Transpose: Wt[n][k] = W[k][n].
// ---------------------------------------------------------------------------
__global__ void __launch_bounds__(256) transpose_kernel(
    const float* __restrict__ W, float* __restrict__ Wt, int K, int N)
{
    __shared__ float t[32][33];
    const int tx = threadIdx.x;
    const int ty = threadIdx.y;
    const int n0 = blockIdx.x * 32;
    const int k0 = blockIdx.y * 32;
    #pragma unroll
    for (int j = 0; j < 32; j += 8)
        t[ty + j][tx] = W[(size_t)(k0 + ty + j) * N + n0 + tx];
    __syncthreads();
    #pragma unroll
    for (int j = 0; j < 32; j += 8)
        Wt[(size_t)(n0 + ty + j) * K + k0 + tx] = t[tx][ty + j];
}

// ---------------------------------------------------------------------------
// Tensor-core GEMM via mma.sync bf16 3-term split (from R3, unchanged).
// ---------------------------------------------------------------------------
#define GSTRIDE   80
#define REG_B     (128 * GSTRIDE)
#define BUF_B     (4 * REG_B)
#define SMEM_DYN  (2 * BUF_B)

__global__ void __launch_bounds__(256) tc_mma_gemm(
    const float* __restrict__ A, const float* __restrict__ Bt,
    float* __restrict__ C, int M, int N, int K)
{
    extern __shared__ __align__(16) char dsm[];

    const int tid = threadIdx.x;
    const int wid = tid >> 5;
    const int lid = tid & 31;
    const int m0 = blockIdx.y * 128;
    const int n0 = blockIdx.x * 128;

    const int wm = wid >> 2;
    const int wn = wid & 3;
    const int Wm = wm * 64;
    const int Wn = wn * 32;

    const uint32_t sbase = smem_u32(dsm);

    const int grow = tid >> 3;
    const int gcol = (tid & 7) * 4;
    const uint32_t soff = (uint32_t)grow * GSTRIDE + (uint32_t)(tid & 7) * 8;

    const int l16 = lid & 15;
    const int kh  = lid >> 4;
    const int bl8 = lid & 7;
    const int bkh = (lid >> 3) & 1;
    const int bnh = lid >> 4;

    float acc[4][4][4];
    #pragma unroll
    for (int i = 0; i < 4; i++)
        #pragma unroll
        for (int j = 0; j < 4; j++)
            #pragma unroll
            for (int c = 0; c < 4; c++) acc[i][j][c] = 0.0f;

    const int NIT = K >> 5;
    float4 av[4], bv[4];

    #pragma unroll
    for (int r = 0; r < 4; r++) {
        av[r] = *(const float4*)(A  + (size_t)(m0 + grow + 32 * r) * K + gcol);
        bv[r] = *(const float4*)(Bt + (size_t)(n0 + grow + 32 * r) * K + gcol);
    }
    {
        char* sb = dsm;
        #pragma unroll
        for (int r = 0; r < 4; r++) {
            uint2 hi, lo;
            const uint32_t o = soff + (uint32_t)(32 * r) * GSTRIDE;
            split4(av[r], hi, lo);
            *(uint2*)(sb + 0 * REG_B + o) = hi;
            *(uint2*)(sb + 1 * REG_B + o) = lo;
            split4(bv[r], hi, lo);
            *(uint2*)(sb + 2 * REG_B + o) = hi;
            *(uint2*)(sb + 3 * REG_B + o) = lo;
        }
    }
    __syncthreads();

    for (int it = 0; it < NIT; it++) {
        if (it + 1 < NIT) {
            const int k0 = (it + 1) * 32;
            #pragma unroll
            for (int r = 0; r < 4; r++) {
                av[r] = *(const float4*)(A  + (size_t)(m0 + grow + 32 * r) * K + k0 + gcol);
                bv[r] = *(const float4*)(Bt + (size_t)(n0 + grow + 32 * r) * K + k0 + gcol);
            }
        }

        const uint32_t buf = sbase + (uint32_t)(it & 1) * BUF_B;
        #pragma unroll
        for (int ks = 0; ks < 2; ks++) {
            const uint32_t akoff = (uint32_t)(ks * 16 + kh * 8) * 2;
            const uint32_t bkoff = (uint32_t)(ks * 16 + bkh * 8) * 2;

            uint32_t ah[4][4], al[4][4];
            #pragma unroll
            for (int mt = 0; mt < 4; mt++) {
                const uint32_t row = (uint32_t)(Wm + mt * 16 + l16) * GSTRIDE + akoff;
                ldsm4(ah[mt], buf + 0 * REG_B + row);
                ldsm4(al[mt], buf + 1 * REG_B + row);
            }
            uint32_t bh[2][4], bl[2][4];
            #pragma unroll
            for (int ng = 0; ng < 2; ng++) {
                const uint32_t row =
                    (uint32_t)(Wn + ng * 16 + bl8 + bnh * 8) * GSTRIDE + bkoff;
                ldsm4(bh[ng], buf + 2 * REG_B + row);
                ldsm4(bl[ng], buf + 3 * REG_B + row);
            }

            #pragma unroll
            for (int mt = 0; mt < 4; mt++)
                #pragma unroll
                for (int ng = 0; ng < 2; ng++)
                    #pragma unroll
                    for (int hf = 0; hf < 2; hf++) {
                        float* c = acc[mt][ng * 2 + hf];
                        const uint32_t bfh[2] = { bh[ng][hf * 2], bh[ng][hf * 2 + 1] };
                        const uint32_t bfl[2] = { bl[ng][hf * 2], bl[ng][hf * 2 + 1] };
                        mma_bf16(c, ah[mt], bfh);
                        mma_bf16(c, ah[mt], bfl);
                        mma_bf16(c, al[mt], bfh);
                    }
        }
        __syncthreads();

        if (it + 1 < NIT) {
            char* sb = dsm + ((it + 1) & 1) * BUF_B;
            #pragma unroll
            for (int r = 0; r < 4; r++) {
                uint2 hi, lo;
                const uint32_t o = soff + (uint32_t)(32 * r) * GSTRIDE;
                split4(av[r], hi, lo);
                *(uint2*)(sb + 0 * REG_B + o) = hi;
                *(uint2*)(sb + 1 * REG_B + o) = lo;
                split4(bv[r], hi, lo);
                *(uint2*)(sb + 2 * REG_B + o) = hi;
                *(uint2*)(sb + 3 * REG_B + o) = lo;
            }
            __syncthreads();
        }
    }

    const int g  = lid >> 2;
    const int tg = (lid & 3) * 2;
    #pragma unroll
    for (int mt = 0; mt < 4; mt++) {
        #pragma unroll
        for (int nt = 0; nt < 4; nt++) {
            const int mrow = m0 + Wm + mt * 16 + g;
            const int ncol = n0 + Wn + nt * 8 + tg;
            float2 v0 = make_float2(acc[mt][nt][0], acc[mt][nt][1]);
            float2 v1 = make_float2(acc[mt][nt][2], acc[mt][nt][3]);
            *(float2*)(C + (size_t)mrow * N + ncol)       = v0;
            *(float2*)(C + (size_t)(mrow + 8) * N + ncol) = v1;
        }
    }
}

// ---------------------------------------------------------------------------
// Prepass 1: split Q (scaled by 0.125*log2e) and K into bf16 hi/lo.
// ---------------------------------------------------------------------------
#define QSCALE (0.125f * 1.44269504088896f)

__global__ void __launch_bounds__(256) qk_split_kernel(
    const float* __restrict__ qkv,
    __nv_bfloat16* __restrict__ qhp, __nv_bfloat16* __restrict__ qlp,
    __nv_bfloat16* __restrict__ khp, __nv_bfloat16* __restrict__ klp)
{
    const int idx = blockIdx.x * 256 + threadIdx.x;  // over NTOK*2048/4
    const int tok = idx >> 9;
    const int c4  = (idx & 511) * 4;
    float4 v = *(const float4*)(qkv + (size_t)tok * QKVROW + c4);
    uint2 hi, lo;
    if (c4 < DMODEL) {
        v.x *= QSCALE; v.y *= QSCALE; v.z *= QSCALE; v.w *= QSCALE;
        split4(v, hi, lo);
        *(uint2*)(qhp + (size_t)tok * DMODEL + c4) = hi;
        *(uint2*)(qlp + (size_t)tok * DMODEL + c4) = lo;
    } else {
        split4(v, hi, lo);
        *(uint2*)(khp + (size_t)tok * DMODEL + c4 - DMODEL) = hi;
        *(uint2*)(klp + (size_t)tok * DMODEL + c4 - DMODEL) = lo;
    }
}

// ---------------------------------------------------------------------------
// Prepass 2: V -> transposed [b,h,d,T] bf16 hi/lo.
// grid (T/32, HD/32, BATCH*NHEAD), block (32,8)
// ---------------------------------------------------------------------------
__global__ void __launch_bounds__(256) v_split_T_kernel(
    const float* __restrict__ qkv,
    __nv_bfloat16* __restrict__ vthp, __nv_bfloat16* __restrict__ vtlp)
{
    __shared__ float t[32][33];
    const int tx = threadIdx.x;
    const int ty = threadIdx.y;
    const int bh = blockIdx.z;
    const int b  = bh >> 4;
    const int h  = bh & 15;
    const int d0 = blockIdx.y * 32;
    const int t0 = blockIdx.x * 32;

    const size_t col = 2 * DMODEL + h * HD + d0 + tx;
    #pragma unroll
    for (int j = 0; j < 32; j += 8)
        t[ty + j][tx] = qkv[(size_t)(b * SEQ + t0 + ty + j) * QKVROW + col];
    __syncthreads();
    #pragma unroll
    for (int j = 0; j < 32; j += 8) {
        const float v = t[tx][ty + j];
        __nv_bfloat16 hi = __float2bfloat16_rn(v);
        __nv_bfloat16 lo = __float2bfloat16_rn(v - __bfloat162float(hi));
        const size_t o = (size_t)(bh * HD + d0 + ty + j) * SEQ + t0 + tx;
        vthp[o] = hi;
        vtlp[o] = lo;
    }
}

// ---------------------------------------------------------------------------
// Flash attention via mma.sync bf16 3-term split.
// CTA: 128 queries x one (b,h). 8 warps, 16 q-rows each. K-tiles of 64.
// SMEM per buffer: Khi,Klo,Vthi,Vtlo: 64 rows x 144B = 9216B each -> 36864B.
// Double buffered via cp.async.
// ---------------------------------------------------------------------------
#define KSTR    144               // smem row stride bytes (72 bf16)
#define REGION  (64 * KSTR)       // 9216
#define ABUF    (4 * REGION)      // 36864
#define ATT_SMEM (2 * ABUF)       // 73728

__global__ void __launch_bounds__(256) attn_mma_kernel(
    const __nv_bfloat16* __restrict__ qh, const __nv_bfloat16* __restrict__ ql,
    const __nv_bfloat16* __restrict__ kh, const __nv_bfloat16* __restrict__ kl,
    const __nv_bfloat16* __restrict__ vth, const __nv_bfloat16* __restrict__ vtl,
    float* __restrict__ y)
{
    extern __shared__ __align__(16) char asm_[];

    const int tid = threadIdx.x;
    const int wid = tid >> 5;
    const int lid = tid & 31;
    const int qt = gridDim.x - 1 - blockIdx.x;   // heavy CTAs first
    const int h  = blockIdx.y;
    const int b  = blockIdx.z;
    const int q0 = qt * 128;
    const int NT = 2 * (qt + 1);

    const uint32_t sb = smem_u32(asm_);

    const int g  = lid >> 2;
    const int c2 = (lid & 3) * 2;
    const int bl8 = lid & 7;
    const int bkh = (lid >> 3) & 1;
    const int bnh = lid >> 4;

    // ---- Q fragments (registers, once) ----
    uint32_t aqh[4][4], aql[4][4];
    {
        const size_t r0 = (size_t)(b * SEQ + q0 + wid * 16 + g) * DMODEL + h * HD;
        const size_t r1 = r0 + 8 * DMODEL;
        #pragma unroll
        for (int ks = 0; ks < 4; ks++) {
            const int k0 = ks * 16 + c2;
            aqh[ks][0] = ld32(qh + r0 + k0);
            aqh[ks][1] = ld32(qh + r1 + k0);
            aqh[ks][2] = ld32(qh + r0 + k0 + 8);
            aqh[ks][3] = ld32(qh + r1 + k0 + 8);
            aql[ks][0] = ld32(ql + r0 + k0);
            aql[ks][1] = ld32(ql + r1 + k0);
            aql[ks][2] = ld32(ql + r0 + k0 + 8);
            aql[ks][3] = ld32(ql + r1 + k0 + 8);
        }
    }

    const size_t kbase = (size_t)(b * SEQ) * DMODEL + h * HD;
    const size_t vbase = (size_t)((b * NHEAD + h) * HD) * SEQ;

    // tile loader (cp.async, one commit group per tile)
    auto load_tile = [&](uint32_t buf, int kt) {
        const int ch = tid & 7;
        const int rr = tid >> 3;   // 0..31
        #pragma unroll
        for (int p = 0; p < 8; p++) {
            const int region = p >> 1;
            const int row = ((p & 1) << 5) + rr;
            const uint32_t dst = buf + region * REGION + row * KSTR + ch * 16;
            const __nv_bfloat16* src;
            if (region == 0)
                src = kh + kbase + (size_t)(kt * 64 + row) * DMODEL + ch * 8;
            else if (region == 1)
                src = kl + kbase + (size_t)(kt * 64 + row) * DMODEL + ch * 8;
            else if (region == 2)
                src = vth + vbase + (size_t)row * SEQ + kt * 64 + ch * 8;
            else
                src = vtl + vbase + (size_t)row * SEQ + kt * 64 + ch * 8;
            cp16(dst, src);
        }
        CP_COMMIT();
    };

    float O[8][4];
    #pragma unroll
    for (int nt = 0; nt < 8; nt++)
        #pragma unroll
        for (int c = 0; c < 4; c++) O[nt][c] = 0.0f;
    float m0 = -INFINITY, m1 = -INFINITY, l0 = 0.0f, l1 = 0.0f;

    load_tile(sb, 0);
    if (NT > 1) load_tile(sb + ABUF, 1);

    for (int kt = 0; kt < NT; kt++) {
        if (kt + 1 < NT) { CP_WAIT1(); } else { CP_WAIT0(); }
        __syncthreads();

        const uint32_t buf = sb + (uint32_t)(kt & 1) * ABUF;

        // ---- S = Qs @ K^T (3-term) ----
        float S[8][4];
        #pragma unroll
        for (int nt = 0; nt < 8; nt++)
            #pragma unroll
            for (int c = 0; c < 4; c++) S[nt][c] = 0.0f;

        #pragma unroll
        for (int ks = 0; ks < 4; ks++) {
            const uint32_t koff = (uint32_t)(ks * 16 + bkh * 8) * 2;
            #pragma unroll
            for (int ng = 0; ng < 4; ng++) {
                const uint32_t row = (uint32_t)(ng * 16 + bl8 + bnh * 8) * KSTR + koff;
                uint32_t kbh[4], kbl[4];
                ldsm4(kbh, buf + 0 * REGION + row);
                ldsm4(kbl, buf + 1 * REGION + row);
                #pragma unroll
                for (int hf = 0; hf < 2; hf++) {
                    float* c = S[ng * 2 + hf];
                    const uint32_t b1[2] = { kbh[hf * 2], kbh[hf * 2 + 1] };
                    const uint32_t b2[2] = { kbl[hf * 2], kbl[hf * 2 + 1] };
                    mma_bf16(c, aqh[ks], b1);   // qh*kh
                    mma_bf16(c, aqh[ks], b2);   // qh*kl
                    mma_bf16(c, aql[ks], b1);   // ql*kh
                }
            }
        }

        // ---- causal mask (last two tiles only) ----
        if (kt >= 2 * qt) {
            const int qr0 = q0 + wid * 16 + g;
            #pragma unroll
            for (int nt = 0; nt < 8; nt++) {
                #pragma unroll
                for (int e = 0; e < 2; e++) {
                    const int key = kt * 64 + nt * 8 + c2 + e;
                    if (key > qr0)     S[nt][e]     = -INFINITY;
                    if (key > qr0 + 8) S[nt][2 + e] = -INFINITY;
                }
            }
        }

        // ---- online softmax (base-2; scale folded into Q) ----
        float mx0 = -INFINITY, mx1 = -INFINITY;
        #pragma unroll
        for (int nt = 0; nt < 8; nt++) {
            mx0 = fmaxf(mx0, fmaxf(S[nt][0], S[nt][1]));
            mx1 = fmaxf(mx1, fmaxf(S[nt][2], S[nt][3]));
        }
        #pragma unroll
        for (int off = 1; off <= 2; off <<= 1) {
            mx0 = fmaxf(mx0, __shfl_xor_sync(0xffffffffu, mx0, off));
            mx1 = fmaxf(mx1, __shfl_xor_sync(0xffffffffu, mx1, off));
        }
        const float mn0 = fmaxf(m0, mx0);
        const float mn1 = fmaxf(m1, mx1);
        const float a0 = exp2f(m0 - mn0);
        const float a1 = exp2f(m1 - mn1);
        m0 = mn0; m1 = mn1;

        float rs0 = 0.0f, rs1 = 0.0f;
        #pragma unroll
        for (int nt = 0; nt < 8; nt++) {
            S[nt][0] = exp2f(S[nt][0] - m0);
            S[nt][1] = exp2f(S[nt][1] - m0);
            S[nt][2] = exp2f(S[nt][2] - m1);
            S[nt][3] = exp2f(S[nt][3] - m1);
            rs0 += S[nt][0] + S[nt][1];
            rs1 += S[nt][2] + S[nt][3];
        }
        #pragma unroll
        for (int off = 1; off <= 2; off <<= 1) {
            rs0 += __shfl_xor_sync(0xffffffffu, rs0, off);
            rs1 += __shfl_xor_sync(0xffffffffu, rs1, off);
        }
        l0 = l0 * a0 + rs0;
        l1 = l1 * a1 + rs1;

        #pragma unroll
        for (int nt = 0; nt < 8; nt++) {
            O[nt][0] *= a0; O[nt][1] *= a0;
            O[nt][2] *= a1; O[nt][3] *= a1;
        }

        // ---- P fragments (hi/lo split) ----
        uint32_t ph[4][4], pl[4][4];
        #pragma unroll
        for (int ks = 0; ks < 4; ks++) {
            #pragma unroll
            for (int r = 0; r < 4; r++) {
                const int nt = ks * 2 + (r >> 1);
                const float p0 = S[nt][(r & 1) * 2 + 0];
                const float p1 = S[nt][(r & 1) * 2 + 1];
                __nv_bfloat16 h0 = __float2bfloat16_rn(p0);
                __nv_bfloat16 h1 = __float2bfloat16_rn(p1);
                __nv_bfloat16 e0 = __float2bfloat16_rn(p0 - __bfloat162float(h0));
                __nv_bfloat16 e1 = __float2bfloat16_rn(p1 - __bfloat162float(h1));
                ph[ks][r] = packbf(h0, h1);
                pl[ks][r] = packbf(e0, e1);
            }
        }
        // note: P A-frag reg order is {(g,c),(g+8,c),(g,c+8),(g+8,c+8)}
        //  r=0 -> nt=2ks   regs (g ,c)  = S[2ks][0..1]
        //  r=1 -> nt=2ks   regs (g8,c)  = S[2ks][2..3]
        //  r=2 -> nt=2ks+1 regs (g ,c)  = S[2ks+1][0..1]
        //  r=3 -> nt=2ks+1 regs (g8,c)  = S[2ks+1][2..3]
        // mapping above: r>>1 picks nt half, r&1 picks row g/g+8. Correct.

        // ---- O += P @ V (3-term) ----
        #pragma unroll
        for (int ks = 0; ks < 4; ks++) {
            const uint32_t koff = (uint32_t)(ks * 16 + bkh * 8) * 2;
            #pragma unroll
            for (int ng = 0; ng < 4; ng++) {
                const uint32_t row = (uint32_t)(ng * 16 + bl8 + bnh * 8) * KSTR + koff;
                uint32_t vbh[4], vbl[4];
                ldsm4(vbh, buf + 2 * REGION + row);
                ldsm4(vbl, buf + 3 * REGION + row);
                #pragma unroll
                for (int hf = 0; hf < 2; hf++) {
                    float* c = O[ng * 2 + hf];
                    const uint32_t b1[2] = { vbh[hf * 2], vbh[hf * 2 + 1] };
                    const uint32_t b2[2] = { vbl[hf * 2], vbl[hf * 2 + 1] };
                    mma_bf16(c, ph[ks], b1);   // ph*vh
                    mma_bf16(c, ph[ks], b2);   // ph*vl
                    mma_bf16(c, pl[ks], b1);   // pl*vh
                }
            }
        }

        __syncthreads();
        if (kt + 2 < NT) load_tile(buf, kt + 2);
    }

    // ---- normalize + store ----
    const float inv0 = 1.0f / l0;
    const float inv1 = 1.0f / l1;
    const size_t o0 = (size_t)(b * SEQ + q0 + wid * 16 + g) * DMODEL + h * HD;
    const size_t o1 = o0 + 8 * DMODEL;
    #pragma unroll
    for (int nt = 0; nt < 8; nt++) {
        float2 v0 = make_float2(O[nt][0] * inv0, O[nt][1] * inv0);
        float2 v1 = make_float2(O[nt][2] * inv1, O[nt][3] * inv1);
        *(float2*)(y + o0 + nt * 8 + c2) = v0;
        *(float2*)(y + o1 + nt * 8 + c2) = v1;
    }
}

// ---------------------------------------------------------------------------
// Launch
// ---------------------------------------------------------------------------
extern "C" void kernel_launch(void* const* d_in, const int* in_sizes, int n_in,
                              void* d_out, int out_size)
{
    const float* x      = (const float*)d_in[0];
    const float* W_attn = (const float*)d_in[1];
    const float* W_proj = (const float*)d_in[2];
    float* out = (float*)d_out;

    void *p_qkv, *p_y, *p_wa, *p_wp, *p_qh, *p_ql, *p_kh, *p_kl, *p_vh, *p_vl;
    cudaGetSymbolAddress(&p_qkv, g_qkv);
    cudaGetSymbolAddress(&p_y,   g_y);
    cudaGetSymbolAddress(&p_wa,  g_wattnT);
    cudaGetSymbolAddress(&p_wp,  g_wprojT);
    cudaGetSymbolAddress(&p_qh,  g_qh);
    cudaGetSymbolAddress(&p_ql,  g_ql);
    cudaGetSymbolAddress(&p_kh,  g_kh);
    cudaGetSymbolAddress(&p_kl,  g_kl);
    cudaGetSymbolAddress(&p_vh,  g_vth);
    cudaGetSymbolAddress(&p_vl,  g_vtl);
    float* qkv = (float*)p_qkv;
    float* y   = (float*)p_y;
    float* waT = (float*)p_wa;
    float* wpT = (float*)p_wp;
    __nv_bfloat16* qh = (__nv_bfloat16*)p_qh;
    __nv_bfloat16* ql = (__nv_bfloat16*)p_ql;
    __nv_bfloat16* kh = (__nv_bfloat16*)p_kh;
    __nv_bfloat16* kl = (__nv_bfloat16*)p_kl;
    __nv_bfloat16* vth = (__nv_bfloat16*)p_vh;
    __nv_bfloat16* vtl = (__nv_bfloat16*)p_vl;

    cudaFuncSetAttribute(tc_mma_gemm,
                         cudaFuncAttributeMaxDynamicSharedMemorySize, SMEM_DYN);
    cudaFuncSetAttribute(attn_mma_kernel,
                         cudaFuncAttributeMaxDynamicSharedMemorySize, ATT_SMEM);

    // 0) transpose weights
    {
        dim3 blk(32, 8);
        transpose_kernel<<<dim3(QKVROW / 32, DMODEL / 32), blk>>>(W_attn, waT, DMODEL, QKVROW);
        transpose_kernel<<<dim3(DMODEL / 32, DMODEL / 32), blk>>>(W_proj, wpT, DMODEL, DMODEL);
    }

    // 1) qkv = x @ W_attn
    {
        dim3 grid(QKVROW / 128, NTOK / 128);
        tc_mma_gemm<<<grid, 256, SMEM_DYN>>>(x, waT, qkv, NTOK, QKVROW, DMODEL);
    }

    // 2) prepass: split/transposed bf16 operands
    qk_split_kernel<<<(NTOK * 2048 / 4) / 256, 256>>>(qkv, qh, ql, kh, kl);
    {
        dim3 blk(32, 8);
        v_split_T_kernel<<<dim3(SEQ / 32, HD / 32, BATCH * NHEAD), blk>>>(qkv, vth, vtl);
    }

    // 3) attention (tensor cores)
    {
        dim3 grid(SEQ / 128, NHEAD, BATCH);
        attn_mma_kernel<<<grid, 256, ATT_SMEM>>>(qh, ql, kh, kl, vth, vtl, y);
    }

    // 4) out = y @ W_proj
    {
        dim3 grid(DMODEL / 128, NTOK / 128);
        tc_mma_gemm<<<grid, 256, SMEM_DYN>>>(y, wpT, out, NTOK, DMODEL, DMODEL);
    }
}